// round 8
// baseline (speedup 1.0000x reference)
#include <cuda_runtime.h>
#include <cuda_fp16.h>
#include <cstdint>

// ============================================================
// VectorQuantizer on GB300 (baseline-PTX path):
//   fp16 mma.sync with F16 ACCUMULATOR, 1024-job grid
//   (256 token-tiles x 4 codebook quarters), per-tile min2 ->
//   contributor top-2 -> quarter top-4 (16 cands/token),
//   threshold-gated exact fp32 rescore. Round 8.
// ============================================================

#define DDIM 256
#define MAXN 32768
#define MAXK 8192
#define DELTA 0.05f

__device__ __half g_zh[(size_t)MAXN * DDIM];   // fp16 tokens
__device__ __half g_ch[(size_t)MAXK * DDIM];   // fp16 codebook
__device__ float  g_cnorm[MAXK];
__device__ unsigned long long g_cand[(size_t)MAXN * 16];  // (fkey|idx) x16
__device__ float  g_part[MAXN];                // per-token loss partial
__device__ double g_lpart[128];                // loss stage-1 partials

// ---------------- PTX helpers ----------------
__device__ __forceinline__ uint32_t smem_u32(const void* p) {
    uint32_t a;
    asm("{ .reg .u64 t; cvta.to.shared.u64 t, %1; cvt.u32.u64 %0, t; }" : "=r"(a) : "l"(p));
    return a;
}
__device__ __forceinline__ void cp16(uint32_t s, const void* g) {
    asm volatile("cp.async.cg.shared.global [%0], [%1], 16;" :: "r"(s), "l"(g) : "memory");
}
__device__ __forceinline__ void cp_commit() {
    asm volatile("cp.async.commit_group;" ::: "memory");
}
template <int N> __device__ __forceinline__ void cp_wait() {
    asm volatile("cp.async.wait_group %0;" :: "n"(N) : "memory");
}
__device__ __forceinline__ void ldsm4(uint32_t a[4], uint32_t addr) {
    asm volatile("ldmatrix.sync.aligned.m8n8.x4.shared.b16 {%0,%1,%2,%3}, [%4];"
                 : "=r"(a[0]), "=r"(a[1]), "=r"(a[2]), "=r"(a[3]) : "r"(addr));
}
// f16-accumulator HMMA: D(f16x2 x2) = A*B + D
__device__ __forceinline__ void mma16816h(uint32_t d[2], const uint32_t a[4],
                                          uint32_t b0, uint32_t b1) {
    asm volatile(
        "mma.sync.aligned.m16n8k16.row.col.f16.f16.f16.f16 "
        "{%0,%1},{%2,%3,%4,%5},{%6,%7},{%0,%1};"
        : "+r"(d[0]), "+r"(d[1])
        : "r"(a[0]), "r"(a[1]), "r"(a[2]), "r"(a[3]), "r"(b0), "r"(b1));
}

__device__ __forceinline__ unsigned fkey(float f) {
    unsigned u = __float_as_uint(f);
    return (u & 0x80000000u) ? ~u : (u | 0x80000000u);
}
__device__ __forceinline__ float unfkey(unsigned k) {
    unsigned u = (k & 0x80000000u) ? (k ^ 0x80000000u) : ~k;
    return __uint_as_float(u);
}

// ---------------- SMEM map for k_argmin ----------------
// [A: 128 x 528 = 67584][B: 2 x (128 x 272) = 69632] = 137216
#define AS 528
#define BS 272
#define A_OFF 0
#define B_OFF 67584
#define B_BYTES 34816
#define SMEM_TOTAL 137216

// ---------------- prep kernels ----------------
__global__ void k_prep_z(const float* __restrict__ z, int n4) {
    int i = blockIdx.x * blockDim.x + threadIdx.x;
    if (i >= n4) return;
    float4 v = ((const float4*)z)[i];
    __half2 a = __floats2half2_rn(v.x, v.y);
    __half2 b = __floats2half2_rn(v.z, v.w);
    uint2 o; o.x = *(uint32_t*)&a; o.y = *(uint32_t*)&b;
    ((uint2*)g_zh)[i] = o;
}

__global__ void k_prep_c(const float* __restrict__ cb, int K) {
    int warp = blockIdx.x * (blockDim.x >> 5) + (threadIdx.x >> 5);
    int lane = threadIdx.x & 31;
    if (warp >= K) return;
    float s = 0.f;
#pragma unroll
    for (int i = 0; i < 2; i++) {
        int e4 = lane + 32 * i;
        float4 v = ((const float4*)(cb + (size_t)warp * DDIM))[e4];
        s += v.x * v.x + v.y * v.y + v.z * v.z + v.w * v.w;
        __half2 a = __floats2half2_rn(v.x, v.y);
        __half2 b = __floats2half2_rn(v.z, v.w);
        uint2 o; o.x = *(uint32_t*)&a; o.y = *(uint32_t*)&b;
        ((uint2*)(g_ch + (size_t)warp * DDIM))[e4] = o;
    }
#pragma unroll
    for (int o = 16; o; o >>= 1) s += __shfl_xor_sync(0xffffffffu, s, o);
    if (lane == 0) g_cnorm[warp] = s;
}

// ---------------- fused fp16 GEMM (f16 accum) + candidates ----------------
// grid = (N/128) * 4; job = 128 tokens x (K/4) codes
__global__ void __launch_bounds__(512, 1) k_argmin(int ntq) {   // ntq = K/512
    extern __shared__ char smem[];
    uint32_t sb = smem_u32(smem);
    int tid = threadIdx.x;
    int lane = tid & 31, wid = tid >> 5;
    int wm = wid >> 2;          // M group (0..3): rows wm*32..+32
    int wn = wid & 3;           // N group (0..3): cols wn*32..+32
    int q4 = blockIdx.x & 3;
    long t0 = (long)(blockIdx.x >> 2) * 128;
    int cq0 = q4 * ntq * 128;   // this job's first code

    // ---- async prologue: A panel + B chunk 0 ----
#pragma unroll
    for (int it = 0; it < 8; it++) {            // A: 128 rows x 32 cp16
        int f = tid + 512 * it;
        int row = f >> 5, c = f & 31;
        cp16(sb + A_OFF + row * AS + c * 16,
             g_zh + (t0 + row) * DDIM + c * 8);
    }
#pragma unroll
    for (int it = 0; it < 4; it++) {            // B chunk q=0: 128 rows x 16 cp16
        int f = tid + 512 * it;
        int row = f >> 4, c = f & 15;
        cp16(sb + B_OFF + row * BS + c * 16,
             g_ch + (size_t)(cq0 + row) * DDIM + c * 8);
    }
    cp_commit();

    // ---- state ----
    uint32_t d[2][4][2];        // f16x2 accumulators
    float ts[4][2];
    int   ti[4][2];
#pragma unroll
    for (int s = 0; s < 4; s++)
#pragma unroll
        for (int e = 0; e < 2; e++) { ts[s][e] = 3.4e38f; ti[s][e] = 0; }

    // ldmatrix lane-address components
    int a_r = (lane & 7) + ((lane >> 3) & 1) * 8;
    int a_k = ((lane >> 4) & 1) * 8;
    int g8  = lane >> 3;                 // 0..3
    int b_ni = g8 >> 1;                  // which n-frag within pair
    int b_kh = (g8 & 1) * 8;             // k-half
    int b_r  = lane & 7;

    int Q = ntq * 2;                     // 128-dim chunks
    for (int q = 0; q < Q; q++) {
        int buf = q & 1;
        if (q + 1 < Q) {
            int nq = q + 1;
            int nkt = nq >> 1, ndc = nq & 1;
            uint32_t bb = sb + B_OFF + (nq & 1) * B_BYTES;
#pragma unroll
            for (int it = 0; it < 4; it++) {
                int f = tid + 512 * it;
                int row = f >> 4, c = f & 15;
                cp16(bb + row * BS + c * 16,
                     g_ch + (size_t)(cq0 + nkt * 128 + row) * DDIM + ndc * 128 + c * 8);
            }
            cp_commit();
            cp_wait<1>();
        } else {
            cp_wait<0>();
        }
        __syncthreads();

        int kt = q >> 1, dc = q & 1;
        if (dc == 0) {
#pragma unroll
            for (int mi = 0; mi < 2; mi++)
#pragma unroll
                for (int ni = 0; ni < 4; ni++) { d[mi][ni][0] = 0u; d[mi][ni][1] = 0u; }
        }
        uint32_t Bb = sb + B_OFF + buf * B_BYTES;

#pragma unroll
        for (int k0 = 0; k0 < 128; k0 += 16) {
            uint32_t a[2][4], bp[2][4];
#pragma unroll
            for (int mi = 0; mi < 2; mi++)
                ldsm4(a[mi], sb + A_OFF + (wm * 32 + mi * 16 + a_r) * AS +
                             (dc * 128 + k0 + a_k) * 2);
#pragma unroll
            for (int p = 0; p < 2; p++)
                ldsm4(bp[p], Bb + (wn * 32 + (p * 2 + b_ni) * 8 + b_r) * BS +
                             (k0 + b_kh) * 2);
            // bp[p] regs: {r0,r1}=(ni=2p, k0/k8), {r2,r3}=(ni=2p+1, k0/k8)
#pragma unroll
            for (int mi = 0; mi < 2; mi++)
#pragma unroll
                for (int ni = 0; ni < 4; ni++)
                    mma16816h(d[mi][ni], a[mi],
                              bp[ni >> 1][(ni & 1) * 2 + 0],
                              bp[ni >> 1][(ni & 1) * 2 + 1]);
        }

        if (dc == 1) {
            // ---- scoring: s = cn - 2*dot; per-slot tile-min2; top-2 ----
            int cbase = cq0 + kt * 128 + wn * 32 + 2 * (lane & 3);
            float2 cn2[4];
#pragma unroll
            for (int ni = 0; ni < 4; ni++)
                cn2[ni] = __ldg((const float2*)&g_cnorm[cbase + ni * 8]);
#pragma unroll
            for (int mi = 0; mi < 2; mi++)
#pragma unroll
                for (int h = 0; h < 2; h++) {
                    int slot = mi * 2 + h;
                    float m1 = 3.4e38f, m2 = 3.4e38f;
                    int i1 = 0, i2 = 0;
#pragma unroll
                    for (int ni = 0; ni < 4; ni++) {
                        float2 dot = __half22float2(
                            *(const __half2*)&d[mi][ni][h]);
                        float s0 = fmaf(-2.f, dot.x, cn2[ni].x);
                        float s1 = fmaf(-2.f, dot.y, cn2[ni].y);
                        int c0 = cbase + ni * 8, c1 = c0 + 1;
                        {
                            bool p1 = s0 < m1, p2 = s0 < m2;
                            float m2n = p2 ? (p1 ? m1 : s0) : m2;
                            int   i2n = p2 ? (p1 ? i1 : c0) : i2;
                            m1 = p1 ? s0 : m1; i1 = p1 ? c0 : i1;
                            m2 = m2n; i2 = i2n;
                        }
                        {
                            bool p1 = s1 < m1, p2 = s1 < m2;
                            float m2n = p2 ? (p1 ? m1 : s1) : m2;
                            int   i2n = p2 ? (p1 ? i1 : c1) : i2;
                            m1 = p1 ? s1 : m1; i1 = p1 ? c1 : i1;
                            m2 = m2n; i2 = i2n;
                        }
                    }
                    // insert tile min2 into persistent top-2 (rarely taken)
#pragma unroll
                    for (int e = 0; e < 2; e++) {
                        float v = e ? m2 : m1;
                        int   c = e ? i2 : i1;
                        if (v < ts[slot][1]) {
                            if (v < ts[slot][0]) {
                                ts[slot][1] = ts[slot][0]; ti[slot][1] = ti[slot][0];
                                ts[slot][0] = v; ti[slot][0] = c;
                            } else { ts[slot][1] = v; ti[slot][1] = c; }
                        }
                    }
                }
        }
        __syncthreads();
    }

    // ---- merge 16 contributors x 2 entries per token -> quarter top-4 ----
    unsigned long long* red = (unsigned long long*)smem;
    int contrib = wn * 4 + (lane & 3);
#pragma unroll
    for (int mi = 0; mi < 2; mi++)
#pragma unroll
        for (int h = 0; h < 2; h++) {
            int slot = mi * 2 + h;
            int token = wm * 32 + mi * 16 + h * 8 + (lane >> 2);
#pragma unroll
            for (int e = 0; e < 2; e++)
                red[token * 32 + contrib * 2 + e] =
                    (((unsigned long long)fkey(ts[slot][e])) << 32) |
                    (unsigned)ti[slot][e];
        }
    __syncthreads();

    if (tid < 128) {
        unsigned long long b1 = ~0ull, b2 = ~0ull, b3 = ~0ull, b4 = ~0ull;
#pragma unroll 4
        for (int j = 0; j < 32; j++) {
            unsigned long long v = red[tid * 32 + j];
            if (v < b4) {
                if (v < b3) {
                    b4 = b3;
                    if (v < b2) { b3 = b2; if (v < b1) { b2 = b1; b1 = v; } else b2 = v; }
                    else b3 = v;
                } else b4 = v;
            }
        }
        unsigned long long* gc = g_cand + ((size_t)(t0 + tid)) * 16 + q4 * 4;
        gc[0] = b1; gc[1] = b2; gc[2] = b3; gc[3] = b4;
    }
}

// ---------------- threshold-gated exact rescore + gather ----------------
__global__ void k_finish(const float* __restrict__ z, const float* __restrict__ cb,
                         float* __restrict__ out_zq, float* __restrict__ out_idx,
                         int has_idx, int N) {
    int warp = blockIdx.x * (blockDim.x >> 5) + (threadIdx.x >> 5);
    int lane = threadIdx.x & 31;
    if (warp >= N) return;
    long t = warp;
    const unsigned long long* c16 = g_cand + (size_t)t * 16;

    float4 xv0 = ((const float4*)z)[t * 64 + lane];
    float4 xv1 = ((const float4*)z)[t * 64 + 32 + lane];

    unsigned long long mn = (lane < 16) ? __ldg(&c16[lane]) : ~0ull;
#pragma unroll
    for (int o = 16; o; o >>= 1)
        mn = min(mn, __shfl_xor_sync(0xffffffffu, mn, o));
    float thr = unfkey((unsigned)(mn >> 32)) + DELTA;

    float best_s = 3.4e38f;
    int best_i = 0x7fffffff;
#pragma unroll 4
    for (int j = 0; j < 16; j++) {
        unsigned long long v = __ldg(&c16[j]);        // uniform -> broadcast
        float ns = unfkey((unsigned)(v >> 32));
        if (ns > thr) continue;
        int ci = (int)(v & 0xffffffffu);
        float4 c0 = __ldg(&((const float4*)cb)[(long)ci * 64 + lane]);
        float4 c1 = __ldg(&((const float4*)cb)[(long)ci * 64 + 32 + lane]);
        float dx, s = 0.f;
        dx = xv0.x - c0.x; s += dx * dx;  dx = xv0.y - c0.y; s += dx * dx;
        dx = xv0.z - c0.z; s += dx * dx;  dx = xv0.w - c0.w; s += dx * dx;
        dx = xv1.x - c1.x; s += dx * dx;  dx = xv1.y - c1.y; s += dx * dx;
        dx = xv1.z - c1.z; s += dx * dx;  dx = xv1.w - c1.w; s += dx * dx;
#pragma unroll
        for (int o = 16; o; o >>= 1) s += __shfl_xor_sync(0xffffffffu, s, o);
        if (s < best_s || (s == best_s && ci < best_i)) { best_s = s; best_i = ci; }
    }

    float4 c0 = __ldg(&((const float4*)cb)[(long)best_i * 64 + lane]);
    float4 c1 = __ldg(&((const float4*)cb)[(long)best_i * 64 + 32 + lane]);
    ((float4*)out_zq)[t * 64 + lane] = c0;
    ((float4*)out_zq)[t * 64 + 32 + lane] = c1;
    if (lane == 0) {
        g_part[t] = best_s;
        if (has_idx) out_idx[t] = (float)best_i;
    }
}

// ---------------- deterministic 2-stage loss reduction ----------------
__global__ void k_loss1(int per_blk) {
    __shared__ double red[256];
    int base = blockIdx.x * per_blk;
    double s = 0.0;
    for (int i = threadIdx.x; i < per_blk; i += 256) s += (double)g_part[base + i];
    red[threadIdx.x] = s;
    __syncthreads();
    for (int o = 128; o; o >>= 1) {
        if (threadIdx.x < o) red[threadIdx.x] += red[threadIdx.x + o];
        __syncthreads();
    }
    if (threadIdx.x == 0) g_lpart[blockIdx.x] = red[0];
}
__global__ void k_loss2(float* __restrict__ out_loss, int N) {
    __shared__ double red[128];
    red[threadIdx.x] = g_lpart[threadIdx.x];
    __syncthreads();
    for (int o = 64; o; o >>= 1) {
        if (threadIdx.x < o) red[threadIdx.x] += red[threadIdx.x + o];
        __syncthreads();
    }
    if (threadIdx.x == 0)
        *out_loss = (float)(1.25 * red[0] / ((double)N * DDIM));
}

// ---------------- launch ----------------
extern "C" void kernel_launch(void* const* d_in, const int* in_sizes, int n_in,
                              void* d_out, int out_size) {
    const float* z  = (const float*)d_in[0];
    const float* cb = (const float*)d_in[1];
    int N = in_sizes[0] / DDIM;
    int K = in_sizes[1] / DDIM;
    float* out = (float*)d_out;

    cudaFuncSetAttribute(k_argmin, cudaFuncAttributeMaxDynamicSharedMemorySize,
                         SMEM_TOTAL);

    int n4 = N * (DDIM / 4);
    k_prep_z<<<(n4 + 255) / 256, 256>>>(z, n4);
    k_prep_c<<<(K + 7) / 8, 256>>>(cb, K);
    k_argmin<<<(N / 128) * 4, 512, SMEM_TOTAL>>>(K / 512);

    long zq_elems = (long)N * DDIM;
    int has_idx  = (out_size >= zq_elems + N);
    int has_loss = (out_size >= zq_elems + N + 1);
    float* out_idx = has_idx ? (out + zq_elems) : nullptr;

    k_finish<<<(N + 7) / 8, 256>>>(z, cb, out, out_idx, has_idx, N);
    if (has_loss) {
        k_loss1<<<128, 256>>>(N / 128);
        k_loss2<<<1, 128>>>(out + zq_elems + N, N);
    }
}

// round 9
// speedup vs baseline: 1.1056x; 1.1056x over previous
#include <cuda_runtime.h>
#include <cuda_fp16.h>
#include <cstdint>

// ============================================================
// VectorQuantizer on GB300 (baseline-PTX path):
//   fp16 mma.sync (f32 accum, rt-saturated) GEMM,
//   1024 quarter-jobs (128 tok x 2048 codes) for wave balance,
//   per-contributor top-2 -> quarter top-4 (16 cands/token),
//   threshold-gated exact fp32 rescore. Round 9.
// ============================================================

#define DDIM 256
#define MAXN 32768
#define MAXK 8192
#define DELTA 0.05f

__device__ __half g_zh[(size_t)MAXN * DDIM];   // fp16 tokens
__device__ __half g_ch[(size_t)MAXK * DDIM];   // fp16 codebook
__device__ float  g_cnorm[MAXK];
__device__ unsigned long long g_cand[(size_t)MAXN * 16];  // (fkey|idx) x16
__device__ float  g_part[MAXN];                // per-token loss partial
__device__ double g_lpart[128];                // loss stage-1 partials

// ---------------- PTX helpers ----------------
__device__ __forceinline__ uint32_t smem_u32(const void* p) {
    uint32_t a;
    asm("{ .reg .u64 t; cvta.to.shared.u64 t, %1; cvt.u32.u64 %0, t; }" : "=r"(a) : "l"(p));
    return a;
}
__device__ __forceinline__ void cp16(uint32_t s, const void* g) {
    asm volatile("cp.async.cg.shared.global [%0], [%1], 16;" :: "r"(s), "l"(g) : "memory");
}
__device__ __forceinline__ void cp_commit() {
    asm volatile("cp.async.commit_group;" ::: "memory");
}
template <int N> __device__ __forceinline__ void cp_wait() {
    asm volatile("cp.async.wait_group %0;" :: "n"(N) : "memory");
}
__device__ __forceinline__ void ldsm4(uint32_t a[4], uint32_t addr) {
    asm volatile("ldmatrix.sync.aligned.m8n8.x4.shared.b16 {%0,%1,%2,%3}, [%4];"
                 : "=r"(a[0]), "=r"(a[1]), "=r"(a[2]), "=r"(a[3]) : "r"(addr));
}
__device__ __forceinline__ void mma16816(float d[4], const uint32_t a[4],
                                         uint32_t b0, uint32_t b1) {
    asm volatile(
        "mma.sync.aligned.m16n8k16.row.col.f32.f16.f16.f32 "
        "{%0,%1,%2,%3},{%4,%5,%6,%7},{%8,%9},{%0,%1,%2,%3};"
        : "+f"(d[0]), "+f"(d[1]), "+f"(d[2]), "+f"(d[3])
        : "r"(a[0]), "r"(a[1]), "r"(a[2]), "r"(a[3]), "r"(b0), "r"(b1));
}

__device__ __forceinline__ unsigned fkey(float f) {
    unsigned u = __float_as_uint(f);
    return (u & 0x80000000u) ? ~u : (u | 0x80000000u);
}
__device__ __forceinline__ float unfkey(unsigned k) {
    unsigned u = (k & 0x80000000u) ? (k ^ 0x80000000u) : ~k;
    return __uint_as_float(u);
}

// ---------------- SMEM map for k_argmin ----------------
// [A: 128 x 528 = 67584][B: 2 x (128 x 272) = 69632] = 137216
#define AS 528
#define BS 272
#define A_OFF 0
#define B_OFF 67584
#define B_BYTES 34816
#define SMEM_TOTAL 137216

// ---------------- merged prep kernel ----------------
// blocks [0, n4/256): z fp32->fp16; blocks [n4/256, +K/8): codebook + norms
__global__ void k_prep(const float* __restrict__ z, const float* __restrict__ cb,
                       int zblocks, int K) {
    if ((int)blockIdx.x < zblocks) {
        int i = blockIdx.x * 256 + threadIdx.x;
        float4 v = ((const float4*)z)[i];
        __half2 a = __floats2half2_rn(v.x, v.y);
        __half2 b = __floats2half2_rn(v.z, v.w);
        uint2 o; o.x = *(uint32_t*)&a; o.y = *(uint32_t*)&b;
        ((uint2*)g_zh)[i] = o;
    } else {
        int warp = (blockIdx.x - zblocks) * 8 + (threadIdx.x >> 5);
        int lane = threadIdx.x & 31;
        if (warp >= K) return;
        float s = 0.f;
#pragma unroll
        for (int i = 0; i < 2; i++) {
            int e4 = lane + 32 * i;
            float4 v = ((const float4*)(cb + (size_t)warp * DDIM))[e4];
            s += v.x * v.x + v.y * v.y + v.z * v.z + v.w * v.w;
            __half2 a = __floats2half2_rn(v.x, v.y);
            __half2 b = __floats2half2_rn(v.z, v.w);
            uint2 o; o.x = *(uint32_t*)&a; o.y = *(uint32_t*)&b;
            ((uint2*)(g_ch + (size_t)warp * DDIM))[e4] = o;
        }
#pragma unroll
        for (int o = 16; o; o >>= 1) s += __shfl_xor_sync(0xffffffffu, s, o);
        if (lane == 0) g_cnorm[warp] = s;
    }
}

// ---------------- fused fp16 GEMM + top-2 argmin (quarter jobs) ----------------
// grid = (N/128)*4; job = 128 tokens x (K/4) codes
__global__ void __launch_bounds__(512, 1) k_argmin(int ntq) {   // ntq = K/512
    extern __shared__ char smem[];
    uint32_t sb = smem_u32(smem);
    int tid = threadIdx.x;
    int lane = tid & 31, wid = tid >> 5;
    int wm = wid >> 2;          // M group (0..3): rows wm*32..+32
    int wn = wid & 3;           // N group (0..3): cols wn*32..+32
    int q4 = blockIdx.x & 3;
    long t0 = (long)(blockIdx.x >> 2) * 128;
    int cq0 = q4 * ntq * 128;   // this job's first code

    // ---- async prologue: A panel + B chunk 0 ----
#pragma unroll
    for (int it = 0; it < 8; it++) {            // A: 128 rows x 32 cp16
        int f = tid + 512 * it;
        int row = f >> 5, c = f & 31;
        cp16(sb + A_OFF + row * AS + c * 16,
             g_zh + (t0 + row) * DDIM + c * 8);
    }
#pragma unroll
    for (int it = 0; it < 4; it++) {            // B chunk q=0: 128 rows x 16 cp16
        int f = tid + 512 * it;
        int row = f >> 4, c = f & 15;
        cp16(sb + B_OFF + row * BS + c * 16,
             g_ch + (size_t)(cq0 + row) * DDIM + c * 8);
    }
    cp_commit();

    // ---- state ----
    float d[2][4][4];
    float ts[4][2];
    int   ti[4][2];
#pragma unroll
    for (int s = 0; s < 4; s++)
#pragma unroll
        for (int e = 0; e < 2; e++) { ts[s][e] = 3.4e38f; ti[s][e] = 0; }

    // ldmatrix lane-address components
    int a_r = (lane & 7) + ((lane >> 3) & 1) * 8;
    int a_k = ((lane >> 4) & 1) * 8;
    int g8  = lane >> 3;                 // 0..3
    int b_ni = g8 >> 1;                  // n-frag within ldsm4 pair
    int b_kh = (g8 & 1) * 8;             // k-half
    int b_r  = lane & 7;

    int Q = ntq * 2;                     // 128-dim chunks
    for (int q = 0; q < Q; q++) {
        int buf = q & 1;
        if (q + 1 < Q) {
            int nq = q + 1;
            int nkt = nq >> 1, ndc = nq & 1;
            uint32_t bb = sb + B_OFF + (nq & 1) * B_BYTES;
#pragma unroll
            for (int it = 0; it < 4; it++) {
                int f = tid + 512 * it;
                int row = f >> 4, c = f & 15;
                cp16(bb + row * BS + c * 16,
                     g_ch + (size_t)(cq0 + nkt * 128 + row) * DDIM + ndc * 128 + c * 8);
            }
            cp_commit();
            cp_wait<1>();
        } else {
            cp_wait<0>();
        }
        __syncthreads();

        int kt = q >> 1, dc = q & 1;
        if (dc == 0) {
#pragma unroll
            for (int mi = 0; mi < 2; mi++)
#pragma unroll
                for (int ni = 0; ni < 4; ni++)
#pragma unroll
                    for (int r = 0; r < 4; r++) d[mi][ni][r] = 0.f;
        }
        uint32_t Bb = sb + B_OFF + buf * B_BYTES;

#pragma unroll
        for (int k0 = 0; k0 < 128; k0 += 16) {
            uint32_t a[2][4], bp[2][4];
#pragma unroll
            for (int mi = 0; mi < 2; mi++)
                ldsm4(a[mi], sb + A_OFF + (wm * 32 + mi * 16 + a_r) * AS +
                             (dc * 128 + k0 + a_k) * 2);
#pragma unroll
            for (int p = 0; p < 2; p++)
                ldsm4(bp[p], Bb + (wn * 32 + (p * 2 + b_ni) * 8 + b_r) * BS +
                             (k0 + b_kh) * 2);
            // bp[p] regs: {r0,r1}=(ni=2p, k0/k8), {r2,r3}=(ni=2p+1, k0/k8)
#pragma unroll
            for (int mi = 0; mi < 2; mi++)
#pragma unroll
                for (int ni = 0; ni < 4; ni++)
                    mma16816(d[mi][ni], a[mi],
                             bp[ni >> 1][(ni & 1) * 2 + 0],
                             bp[ni >> 1][(ni & 1) * 2 + 1]);
        }

        if (dc == 1) {
            // ---- scoring: s = cn - 2*dot, per-slot min, top-2 ----
            int cbase = cq0 + kt * 128 + wn * 32 + 2 * (lane & 3);
            float2 cn2[4];
#pragma unroll
            for (int ni = 0; ni < 4; ni++)
                cn2[ni] = __ldg((const float2*)&g_cnorm[cbase + ni * 8]);
#pragma unroll
            for (int mi = 0; mi < 2; mi++)
#pragma unroll
                for (int h = 0; h < 2; h++) {
                    int slot = mi * 2 + h;
                    float bs = 3.4e38f; int bc = 0;
#pragma unroll
                    for (int ni = 0; ni < 4; ni++) {
                        float s0 = fmaf(-2.f, d[mi][ni][h * 2 + 0], cn2[ni].x);
                        float s1 = fmaf(-2.f, d[mi][ni][h * 2 + 1], cn2[ni].y);
                        int c0 = cbase + ni * 8, c1 = c0 + 1;
                        if (s0 < bs) { bs = s0; bc = c0; }
                        if (s1 < bs) { bs = s1; bc = c1; }
                    }
                    if (bs < ts[slot][1]) {
                        if (bs < ts[slot][0]) {
                            ts[slot][1] = ts[slot][0]; ti[slot][1] = ti[slot][0];
                            ts[slot][0] = bs; ti[slot][0] = bc;
                        } else { ts[slot][1] = bs; ti[slot][1] = bc; }
                    }
                }
        }
        __syncthreads();
    }

    // ---- merge 16 contributors x 2 entries per token -> quarter top-4 ----
    unsigned long long* red = (unsigned long long*)smem;
    int contrib = wn * 4 + (lane & 3);
#pragma unroll
    for (int mi = 0; mi < 2; mi++)
#pragma unroll
        for (int h = 0; h < 2; h++) {
            int slot = mi * 2 + h;
            int token = wm * 32 + mi * 16 + h * 8 + (lane >> 2);
#pragma unroll
            for (int e = 0; e < 2; e++)
                red[token * 32 + contrib * 2 + e] =
                    (((unsigned long long)fkey(ts[slot][e])) << 32) |
                    (unsigned)ti[slot][e];
        }
    __syncthreads();

    if (tid < 128) {
        unsigned long long b1 = ~0ull, b2 = ~0ull, b3 = ~0ull, b4 = ~0ull;
#pragma unroll 4
        for (int j = 0; j < 32; j++) {
            unsigned long long v = red[tid * 32 + j];
            if (v < b4) {
                if (v < b3) {
                    b4 = b3;
                    if (v < b2) { b3 = b2; if (v < b1) { b2 = b1; b1 = v; } else b2 = v; }
                    else b3 = v;
                } else b4 = v;
            }
        }
        unsigned long long* gc = g_cand + ((size_t)(t0 + tid)) * 16 + q4 * 4;
        gc[0] = b1; gc[1] = b2; gc[2] = b3; gc[3] = b4;
    }
}

// ---------------- threshold-gated exact rescore + gather ----------------
__global__ void k_finish(const float* __restrict__ z, const float* __restrict__ cb,
                         float* __restrict__ out_zq, float* __restrict__ out_idx,
                         int has_idx, int N) {
    int warp = blockIdx.x * (blockDim.x >> 5) + (threadIdx.x >> 5);
    int lane = threadIdx.x & 31;
    if (warp >= N) return;
    long t = warp;
    const unsigned long long* c16 = g_cand + (size_t)t * 16;

    float4 xv0 = ((const float4*)z)[t * 64 + lane];
    float4 xv1 = ((const float4*)z)[t * 64 + 32 + lane];

    unsigned long long mn = (lane < 16) ? __ldg(&c16[lane]) : ~0ull;
#pragma unroll
    for (int o = 16; o; o >>= 1)
        mn = min(mn, __shfl_xor_sync(0xffffffffu, mn, o));
    float thr = unfkey((unsigned)(mn >> 32)) + DELTA;

    float best_s = 3.4e38f;
    int best_i = 0x7fffffff;
#pragma unroll 4
    for (int j = 0; j < 16; j++) {
        unsigned long long v = __ldg(&c16[j]);        // uniform -> broadcast
        float ns = unfkey((unsigned)(v >> 32));
        if (ns > thr) continue;
        int ci = (int)(v & 0xffffffffu);
        float4 c0 = __ldg(&((const float4*)cb)[(long)ci * 64 + lane]);
        float4 c1 = __ldg(&((const float4*)cb)[(long)ci * 64 + 32 + lane]);
        float dx, s = 0.f;
        dx = xv0.x - c0.x; s += dx * dx;  dx = xv0.y - c0.y; s += dx * dx;
        dx = xv0.z - c0.z; s += dx * dx;  dx = xv0.w - c0.w; s += dx * dx;
        dx = xv1.x - c1.x; s += dx * dx;  dx = xv1.y - c1.y; s += dx * dx;
        dx = xv1.z - c1.z; s += dx * dx;  dx = xv1.w - c1.w; s += dx * dx;
#pragma unroll
        for (int o = 16; o; o >>= 1) s += __shfl_xor_sync(0xffffffffu, s, o);
        if (s < best_s || (s == best_s && ci < best_i)) { best_s = s; best_i = ci; }
    }

    float4 c0 = __ldg(&((const float4*)cb)[(long)best_i * 64 + lane]);
    float4 c1 = __ldg(&((const float4*)cb)[(long)best_i * 64 + 32 + lane]);
    ((float4*)out_zq)[t * 64 + lane] = c0;
    ((float4*)out_zq)[t * 64 + 32 + lane] = c1;
    if (lane == 0) {
        g_part[t] = best_s;
        if (has_idx) out_idx[t] = (float)best_i;
    }
}

// ---------------- deterministic 2-stage loss reduction ----------------
__global__ void k_loss1(int per_blk) {
    __shared__ double red[256];
    int base = blockIdx.x * per_blk;
    double s = 0.0;
    for (int i = threadIdx.x; i < per_blk; i += 256) s += (double)g_part[base + i];
    red[threadIdx.x] = s;
    __syncthreads();
    for (int o = 128; o; o >>= 1) {
        if (threadIdx.x < o) red[threadIdx.x] += red[threadIdx.x + o];
        __syncthreads();
    }
    if (threadIdx.x == 0) g_lpart[blockIdx.x] = red[0];
}
__global__ void k_loss2(float* __restrict__ out_loss, int N) {
    __shared__ double red[128];
    red[threadIdx.x] = g_lpart[threadIdx.x];
    __syncthreads();
    for (int o = 64; o; o >>= 1) {
        if (threadIdx.x < o) red[threadIdx.x] += red[threadIdx.x + o];
        __syncthreads();
    }
    if (threadIdx.x == 0)
        *out_loss = (float)(1.25 * red[0] / ((double)N * DDIM));
}

// ---------------- launch ----------------
extern "C" void kernel_launch(void* const* d_in, const int* in_sizes, int n_in,
                              void* d_out, int out_size) {
    const float* z  = (const float*)d_in[0];
    const float* cb = (const float*)d_in[1];
    int N = in_sizes[0] / DDIM;
    int K = in_sizes[1] / DDIM;
    float* out = (float*)d_out;

    cudaFuncSetAttribute(k_argmin, cudaFuncAttributeMaxDynamicSharedMemorySize,
                         SMEM_TOTAL);

    int n4 = N * (DDIM / 4);
    int zblocks = (n4 + 255) / 256;
    k_prep<<<zblocks + (K + 7) / 8, 256>>>(z, cb, zblocks, K);
    k_argmin<<<(N / 128) * 4, 512, SMEM_TOTAL>>>(K / 512);

    long zq_elems = (long)N * DDIM;
    int has_idx  = (out_size >= zq_elems + N);
    int has_loss = (out_size >= zq_elems + N + 1);
    float* out_idx = has_idx ? (out + zq_elems) : nullptr;

    k_finish<<<(N + 7) / 8, 256>>>(z, cb, out, out_idx, has_idx, N);
    if (has_loss) {
        k_loss1<<<128, 256>>>(N / 128);
        k_loss2<<<1, 128>>>(out + zq_elems + N, N);
    }
}